// round 1
// baseline (speedup 1.0000x reference)
#include <cuda_runtime.h>
#include <cstddef>

// Scratch: E = enc@W^T (2048x1024), D = dec@W^T + bias (512x1024)
__device__ float g_E[2048 * 1024];
__device__ float g_D[512 * 1024];

// ---------------------------------------------------------------------------
// GEMM: C[M x 1024] = A[M x 512] @ B[1024 x 512]^T (+ optional bias)
// Both A and B are K-contiguous (NT GEMM). 128x128 tile, BK=16, 256 thr, 8x8.
// ---------------------------------------------------------------------------
constexpr int BM = 128, BN = 128, BK = 16, TM = 8, TN = 8;

__global__ void __launch_bounds__(256, 2)
gemm_nt(const float* __restrict__ A, const float* __restrict__ B,
        const float* __restrict__ bias, float* __restrict__ C) {
    constexpr int K = 512, N = 1024;
    __shared__ float As[BK][BM + 4];
    __shared__ float Bs[BK][BN + 4];

    const int tid  = threadIdx.x;
    const int row0 = blockIdx.y * BM;
    const int col0 = blockIdx.x * BN;
    const int tx = tid & 15, ty = tid >> 4;

    float acc[TM][TN];
#pragma unroll
    for (int i = 0; i < TM; i++)
#pragma unroll
        for (int j = 0; j < TN; j++) acc[i][j] = 0.f;

    for (int k0 = 0; k0 < K; k0 += BK) {
        // Load 128x16 A-tile and 128x16 B-tile (512 float4 each; 2 per thread)
#pragma unroll
        for (int p = 0; p < 2; p++) {
            int f  = tid + p * 256;
            int r  = f >> 2;
            int kq = (f & 3) * 4;
            float4 a = *(const float4*)(A + (size_t)(row0 + r) * K + k0 + kq);
            As[kq + 0][r] = a.x; As[kq + 1][r] = a.y;
            As[kq + 2][r] = a.z; As[kq + 3][r] = a.w;
            float4 bb = *(const float4*)(B + (size_t)(col0 + r) * K + k0 + kq);
            Bs[kq + 0][r] = bb.x; Bs[kq + 1][r] = bb.y;
            Bs[kq + 2][r] = bb.z; Bs[kq + 3][r] = bb.w;
        }
        __syncthreads();

#pragma unroll
        for (int kk = 0; kk < BK; kk++) {
            float ra[TM], rb[TN];
#pragma unroll
            for (int i = 0; i < TM; i++) ra[i] = As[kk][ty * TM + i];
#pragma unroll
            for (int j = 0; j < TN; j++) rb[j] = Bs[kk][tx * TN + j];
#pragma unroll
            for (int i = 0; i < TM; i++)
#pragma unroll
                for (int j = 0; j < TN; j++) acc[i][j] += ra[i] * rb[j];
        }
        __syncthreads();
    }

#pragma unroll
    for (int i = 0; i < TM; i++) {
        int r = row0 + ty * TM + i;
#pragma unroll
        for (int j = 0; j < TN; j += 4) {
            int c = col0 + tx * TN + j;
            float4 v = make_float4(acc[i][j], acc[i][j + 1],
                                   acc[i][j + 2], acc[i][j + 3]);
            if (bias) {
                v.x += bias[c + 0]; v.y += bias[c + 1];
                v.z += bias[c + 2]; v.w += bias[c + 3];
            }
            *(float4*)(C + (size_t)r * N + c) = v;
        }
    }
}

// ---------------------------------------------------------------------------
// Broadcast add: out[b,t,u,v] = E[b*256+t, v] + D[b*64+u, v]
// Each block: one (b, 8-row t-tile); 256 threads each own a float4 v-slice.
// E rows cached in registers; D rows stream from L2 (2 MB resident).
// ---------------------------------------------------------------------------
constexpr int TT = 8;  // t rows per block

__global__ void __launch_bounds__(256)
bcast_add(const float* __restrict__ E, const float* __restrict__ D,
          float* __restrict__ out) {
    const int tile = blockIdx.x;            // 0..255
    const int b    = tile / (256 / TT);     // 0..7
    const int t0   = (tile % (256 / TT)) * TT;
    const int v4   = threadIdx.x;           // float4 lane: v = 4*v4

    const float4* E4 = (const float4*)E;
    const float4* D4 = (const float4*)D;
    float4*       O4 = (float4*)out;

    float4 e[TT];
#pragma unroll
    for (int i = 0; i < TT; i++)
        e[i] = E4[(size_t)(b * 256 + t0 + i) * 256 + v4];

    const size_t base = ((size_t)(b * 256 + t0) * 64) * 256 + v4;

    for (int u = 0; u < 64; u++) {
        float4 d = D4[(size_t)(b * 64 + u) * 256 + v4];
        size_t ou = base + (size_t)u * 256;
#pragma unroll
        for (int i = 0; i < TT; i++) {
            float4 r = make_float4(e[i].x + d.x, e[i].y + d.y,
                                   e[i].z + d.z, e[i].w + d.w);
            O4[ou + (size_t)i * 64 * 256] = r;
        }
    }
}

// ---------------------------------------------------------------------------
extern "C" void kernel_launch(void* const* d_in, const int* in_sizes, int n_in,
                              void* d_out, int out_size) {
    const float* enc  = (const float*)d_in[0];  // (8,256,512)
    const float* dec  = (const float*)d_in[1];  // (8,64,512)
    const float* W    = (const float*)d_in[2];  // (1024,512)
    const float* bias = (const float*)d_in[3];  // (1024,)
    float* out = (float*)d_out;                 // (8,256,64,1024)

    float *E, *D;
    cudaGetSymbolAddress((void**)&E, g_E);
    cudaGetSymbolAddress((void**)&D, g_D);

    // E = enc_flat(2048x512) @ W^T          -> grid (1024/BN, 2048/BM)
    gemm_nt<<<dim3(1024 / BN, 2048 / BM), 256>>>(enc, W, nullptr, E);
    // D = dec_flat(512x512) @ W^T + bias    -> grid (1024/BN, 512/BM)
    gemm_nt<<<dim3(1024 / BN, 512 / BM), 256>>>(dec, W, bias, D);
    // out = E (broadcast over u) + D (broadcast over t)
    bcast_add<<<256, 256>>>(E, D, out);
}